// round 2
// baseline (speedup 1.0000x reference)
#include <cuda_runtime.h>

#define EPSLN 1e-5f
typedef unsigned long long ull;

// Precomputed per launch (deterministic, graph-capturable)
__device__ __align__(16) ulonglong2 g_W2[64 * 16];  // [col][swz(i2h)] f32x2 pairs
__device__ __align__(16) float      g_ewproj[16];   // We_w @ attn_w[128:192]

__device__ __forceinline__ ull packf2(float lo, float hi) {
    ull r; asm("mov.b64 %0, {%1, %2};" : "=l"(r) : "f"(lo), "f"(hi)); return r;
}
__device__ __forceinline__ float f2lo(ull v) { return __uint_as_float((unsigned)v); }
__device__ __forceinline__ float f2hi(ull v) { return __uint_as_float((unsigned)(v >> 32)); }

// Packed dual-fp32 FMA (Blackwell f32x2): d = a*b + d elementwise
#define FFMA2(d, a, b) asm("fma.rn.f32x2 %0, %1, %2, %0;" : "+l"(d) : "l"(a), "l"(b))

__global__ void prep_kernel(const float* __restrict__ Ww,
                            const float* __restrict__ Wew,
                            const float* __restrict__ attw) {
    int c = threadIdx.x;  // 64 threads = output columns
    if (c < 16) {
        float se = 0.f;
#pragma unroll 8
        for (int o = 0; o < 64; ++o) se += Wew[c * 64 + o] * attw[128 + o];
        g_ewproj[c] = se;
    }
    // g_W2[col][i2h ^ ((col>>1)&7)] = {(W[4j][c],W[4j+1][c]), (W[4j+2][c],W[4j+3][c])}
#pragma unroll
    for (int j = 0; j < 16; ++j) {
        ulonglong2 v;
        v.x = packf2(Ww[(4 * j + 0) * 64 + c], Ww[(4 * j + 1) * 64 + c]);
        v.y = packf2(Ww[(4 * j + 2) * 64 + c], Ww[(4 * j + 3) * 64 + c]);
        g_W2[c * 16 + (j ^ ((c >> 1) & 7))] = v;
    }
}

__global__ __launch_bounds__(256) void gat_kernel(
    const float* __restrict__ nodes,
    const float* __restrict__ edges,
    const float* __restrict__ Wbias,
    const float* __restrict__ attw,
    const float* __restrict__ gamma,
    const float* __restrict__ beta,
    float* __restrict__ out)
{
    __shared__ ulonglong2 sW[64 * 16];      // 16 KB weights (shared by both batches)
    __shared__ float  sScore[2][32];
    __shared__ float  sAttn[2][32];
    __shared__ float2 sMsg[2][4][32];

    const int tid  = threadIdx.x;
    const int lane = tid & 31;
    const int bl   = tid >> 7;              // which batch in this CTA
    const int w4   = (tid >> 5) & 3;        // warp within batch
    const long long b = (long long)blockIdx.x * 2 + bl;

    // stage weights (16 KB, once per CTA)
    for (int t = tid; t < 64 * 16; t += 256) sW[t] = g_W2[t];

    // rows: warp0 -> 9 rows (incl. target row 0), warps 1..3 -> 8 rows each
    const int rowBase = (w4 == 0) ? 0 : 9 + (w4 - 1) * 8;
    const int nrows   = (w4 == 0) ? 9 : 8;

    // load X rows straight into registers (dup-coalesced LDG.128)
    const float* gN = nodes + b * 2112;     // 33*64
    ull x0[9], x1[9];
#pragma unroll
    for (int j = 0; j < 9; ++j) {
        if (j < nrows) {
            ulonglong2 v = *(const ulonglong2*)(gN + (rowBase + j) * 64 + 4 * (lane & 15));
            x0[j] = v.x; x1[j] = v.y;
        }
    }

    // warp0: edge score term e_k = edges[k] . ewproj (kept in register)
    float ek = 0.f;
    if (w4 == 0) {
        const float4* er = (const float4*)(edges + (b * 32 + lane) * 16);
#pragma unroll
        for (int e4 = 0; e4 < 4; ++e4) {
            float4 a = er[e4];
            float4 w = *(const float4*)&g_ewproj[e4 * 4];
            ek += a.x * w.x + a.y * w.y + a.z * w.z + a.w * w.w;
        }
    }

    __syncthreads();  // weights staged

    // ---- GEMM: lane owns cols (2*lane, 2*lane+1); X broadcast via shuffles ----
    ull acc0[9], acc1[9];
#pragma unroll
    for (int j = 0; j < 9; ++j) { acc0[j] = 0ull; acc1[j] = 0ull; }

    const ulonglong2* w0p = sW + (2 * lane) * 16;
    const int sw = lane & 7;   // == ((2*lane)>>1)&7 == ((2*lane+1)>>1)&7

#pragma unroll
    for (int i2h = 0; i2h < 16; ++i2h) {
        ulonglong2 wa = w0p[i2h ^ sw];          // col 2*lane,   i = 4*i2h .. +3
        ulonglong2 wb = w0p[16 + (i2h ^ sw)];   // col 2*lane+1
#pragma unroll
        for (int j = 0; j < 9; ++j) {
            if (j < nrows) {
                ull a01 = __shfl_sync(0xffffffffu, x0[j], i2h);
                ull a23 = __shfl_sync(0xffffffffu, x1[j], i2h);
                FFMA2(acc0[j], a01, wa.x);
                FFMA2(acc0[j], a23, wa.y);
                FFMA2(acc1[j], a01, wb.x);
                FFMA2(acc1[j], a23, wb.y);
            }
        }
    }

    // ---- epilogue ----
    const float2 wb2  = *(const float2*)(Wbias + 2 * lane);
    const float2 awn2 = *(const float2*)(attw + 64 + 2 * lane);
    const float2 g2   = *(const float2*)(gamma + 2 * lane);
    const float2 be2  = *(const float2*)(beta  + 2 * lane);
    float* gO = out + b * 2112;

    float h0[9], h1[9];
#pragma unroll
    for (int j = 0; j < 9; ++j) {
        if (j < nrows) {
            h0[j] = f2lo(acc0[j]) + f2hi(acc0[j]) + wb2.x;
            h1[j] = f2lo(acc1[j]) + f2hi(acc1[j]) + wb2.y;
            int row = rowBase + j;
            if (row >= 1) {
                // attention score (node part): s = h . aw_n, warp-reduced
                float s = fmaf(h0[j], awn2.x, h1[j] * awn2.y);
                // layernorm stats for this row (independent of attention)
                float sm = h0[j] + h1[j];
                float s2 = fmaf(h0[j], h0[j], h1[j] * h1[j]);
#pragma unroll
                for (int d = 16; d > 0; d >>= 1) {
                    s  += __shfl_xor_sync(0xffffffffu, s,  d);
                    sm += __shfl_xor_sync(0xffffffffu, sm, d);
                    s2 += __shfl_xor_sync(0xffffffffu, s2, d);
                }
                if (lane == 0) sScore[bl][row - 1] = s;
                float mu  = sm * (1.f / 64.f);
                float var = fmaf(s2, 1.f / 64.f, -mu * mu);
                float r   = rsqrtf(var + EPSLN);
                float2 o;
                o.x = fmaf((h0[j] - mu) * r, g2.x, be2.x);
                o.y = fmaf((h1[j] - mu) * r, g2.y, be2.y);
                *(float2*)(gO + row * 64 + 2 * lane) = o;
            }
        }
    }
    __syncthreads();

    // warp0 of each batch: softmax over the 32 scores
    if (w4 == 0) {
        float s = sScore[bl][lane] + ek;
        float m = s;
#pragma unroll
        for (int d = 16; d > 0; d >>= 1) m = fmaxf(m, __shfl_xor_sync(0xffffffffu, m, d));
        float p = __expf(s - m);
        float tot = p;
#pragma unroll
        for (int d = 16; d > 0; d >>= 1) tot += __shfl_xor_sync(0xffffffffu, tot, d);
        sAttn[bl][lane] = p / tot;
    }
    __syncthreads();

    // message partials from registers
    float pm0 = 0.f, pm1 = 0.f;
#pragma unroll
    for (int j = 0; j < 9; ++j) {
        if (j < nrows) {
            int row = rowBase + j;
            if (row >= 1) {
                float a = sAttn[bl][row - 1];
                pm0 = fmaf(a, h0[j], pm0);
                pm1 = fmaf(a, h1[j], pm1);
            }
        }
    }
    sMsg[bl][w4][lane] = make_float2(pm0, pm1);
    __syncthreads();

    // row 0: target + message, layernorm
    if (w4 == 0) {
        float m0 = (sMsg[bl][0][lane].x + sMsg[bl][1][lane].x) +
                   (sMsg[bl][2][lane].x + sMsg[bl][3][lane].x);
        float m1 = (sMsg[bl][0][lane].y + sMsg[bl][1][lane].y) +
                   (sMsg[bl][2][lane].y + sMsg[bl][3][lane].y);
        float a0 = h0[0] + m0;
        float a1 = h1[0] + m1;
        float sm = a0 + a1;
        float s2 = fmaf(a0, a0, a1 * a1);
#pragma unroll
        for (int d = 16; d > 0; d >>= 1) {
            sm += __shfl_xor_sync(0xffffffffu, sm, d);
            s2 += __shfl_xor_sync(0xffffffffu, s2, d);
        }
        float mu  = sm * (1.f / 64.f);
        float var = fmaf(s2, 1.f / 64.f, -mu * mu);
        float r   = rsqrtf(var + EPSLN);
        float2 o;
        o.x = fmaf((a0 - mu) * r, g2.x, be2.x);
        o.y = fmaf((a1 - mu) * r, g2.y, be2.y);
        *(float2*)(gO + 2 * lane) = o;
    }
}

extern "C" void kernel_launch(void* const* d_in, const int* in_sizes, int n_in,
                              void* d_out, int out_size) {
    const float* nodes = (const float*)d_in[0];
    const float* edges = (const float*)d_in[1];
    const float* Ww    = (const float*)d_in[2];
    const float* Wb    = (const float*)d_in[3];
    const float* Wew   = (const float*)d_in[4];
    // d_in[5] = We_b   (cancels under softmax shift-invariance)
    const float* attw  = (const float*)d_in[6];
    // d_in[7] = attn_b (cancels under softmax shift-invariance)
    const float* gamma = (const float*)d_in[8];
    const float* beta  = (const float*)d_in[9];

    prep_kernel<<<1, 64>>>(Ww, Wew, attw);
    gat_kernel<<<16384 / 2, 256>>>(nodes, edges, Wb, attw, gamma, beta, (float*)d_out);
}

// round 3
// speedup vs baseline: 1.6683x; 1.6683x over previous
#include <cuda_runtime.h>

#define EPSLN 1e-5f

// Precomputed per launch (deterministic, graph-capturable)
__device__ __align__(16) uint2 g_Wfrag[8 * 8 * 32];  // [ks][nt][lane] tf32 B-fragments
__device__ __align__(16) float g_ewproj[16];         // We_w @ attn_w[128:192]

__device__ __forceinline__ unsigned cvt_tf32(float x) {
    unsigned r; asm("cvt.rna.tf32.f32 %0, %1;" : "=r"(r) : "f"(x)); return r;
}

#define MMA_TF32(d, a, b)                                                          \
    asm volatile(                                                                  \
        "mma.sync.aligned.m16n8k8.row.col.f32.tf32.tf32.f32 "                      \
        "{%0,%1,%2,%3},{%4,%5,%6,%7},{%8,%9},{%0,%1,%2,%3};"                       \
        : "+f"(d[0]), "+f"(d[1]), "+f"(d[2]), "+f"(d[3])                           \
        : "r"(a[0]), "r"(a[1]), "r"(a[2]), "r"(a[3]), "r"(b[0]), "r"(b[1]))

__global__ void prep_kernel(const float* __restrict__ Ww,
                            const float* __restrict__ Wew,
                            const float* __restrict__ attw) {
    int tid = threadIdx.x;  // 256
    if (tid < 16) {
        float se = 0.f;
#pragma unroll 8
        for (int o = 0; o < 64; ++o) se += Wew[tid * 64 + o] * attw[128 + o];
        g_ewproj[tid] = se;
    }
    // B fragment for m16n8k8.row.col: b0 = B[k=t][n=g], b1 = B[k=t+4][n=g]
    // (t = lane%4, g = lane/4), tile (ks, nt): k += ks*8, n += nt*8
    for (int idx = tid; idx < 2048; idx += 256) {
        int lane = idx & 31;
        int nt   = (idx >> 5) & 7;
        int ks   = idx >> 8;
        int t = lane & 3, g = lane >> 2;
        uint2 v;
        v.x = cvt_tf32(Ww[(ks * 8 + t) * 64 + nt * 8 + g]);
        v.y = cvt_tf32(Ww[(ks * 8 + t + 4) * 64 + nt * 8 + g]);
        g_Wfrag[idx] = v;
    }
}

__global__ __launch_bounds__(128) void gat_kernel(
    const float* __restrict__ nodes,
    const float* __restrict__ edges,
    const float* __restrict__ Wbias,
    const float* __restrict__ attw,
    const float* __restrict__ gamma,
    const float* __restrict__ beta,
    float* __restrict__ out)
{
    __shared__ float  sN[2][33 * 68];        // nodes, stride 68 (bank-tuned)
    __shared__ uint2  sB[8 * 8 * 32];        // weight fragments (16 KB)
    __shared__ float4 sStats[2][2][33];      // (sum, sumsq, score, -) per row/half
    __shared__ float  sAttn[2][32];
    __shared__ float2 sT[2][2];              // target LN partials per half

    const int tid  = threadIdx.x;
    const int lane = tid & 31;
    const int warp = tid >> 5;
    const int bl   = warp >> 1;     // batch within CTA
    const int half = warp & 1;      // column half (32 cols)
    const int t    = lane & 3;      // threadID-in-group
    const int g    = lane >> 2;     // groupID
    const long long b = (long long)blockIdx.x * 2 + bl;

    // ---- stage weights (all 128 threads) ----
    for (int q = tid; q < 2048; q += 128) sB[q] = g_Wfrag[q];

    // ---- stage nodes: 2 batches x 33 rows x 64 -> smem stride 68 ----
    for (int q = tid; q < 1056; q += 128) {   // 1056 float4 total
        int bb = q >= 528;
        int ql = q - bb * 528;
        int r  = ql >> 4;
        int i4 = ql & 15;
        float4 v = ((const float4*)(nodes + ((long long)blockIdx.x * 2 + bb) * 2112))[ql];
        *(float4*)&sN[bb][r * 68 + i4 * 4] = v;
    }

    // ---- edge score term (half==0 warps, lane = neighbor k) ----
    float ek = 0.f;
    if (half == 0) {
        const float4* er = (const float4*)(edges + (b * 32 + lane) * 16);
#pragma unroll
        for (int e4 = 0; e4 < 4; ++e4) {
            float4 a = er[e4];
            float4 w = *(const float4*)&g_ewproj[e4 * 4];
            ek += a.x * w.x + a.y * w.y + a.z * w.z + a.w * w.w;
        }
    }
    __syncthreads();

    // ---- tensor-core GEMM: 3 m16 tiles x 4 n8 tiles (this warp's half) ----
    const float* sNb = sN[bl];
    float d[3][4][4];
#pragma unroll
    for (int m = 0; m < 3; ++m)
#pragma unroll
        for (int j = 0; j < 4; ++j)
#pragma unroll
            for (int c = 0; c < 4; ++c) d[m][j][c] = 0.f;

#pragma unroll
    for (int ks = 0; ks < 8; ++ks) {
        unsigned bb[4][2];
#pragma unroll
        for (int j = 0; j < 4; ++j) {
            uint2 v = sB[(ks * 8 + half * 4 + j) * 32 + lane];
            bb[j][0] = v.x; bb[j][1] = v.y;
        }
        unsigned aa[3][4];
#pragma unroll
        for (int m = 0; m < 2; ++m) {
            int base = (m * 16 + g) * 68 + ks * 8 + t;
            aa[m][0] = cvt_tf32(sNb[base]);
            aa[m][1] = cvt_tf32(sNb[base + 8 * 68]);
            aa[m][2] = cvt_tf32(sNb[base + 4]);
            aa[m][3] = cvt_tf32(sNb[base + 8 * 68 + 4]);
        }
        // mtile 2: only row 32 (g==0) is real; others zero
        if (g == 0) {
            int base = 32 * 68 + ks * 8 + t;
            aa[2][0] = cvt_tf32(sNb[base]);
            aa[2][2] = cvt_tf32(sNb[base + 4]);
        } else { aa[2][0] = 0u; aa[2][2] = 0u; }
        aa[2][1] = 0u; aa[2][3] = 0u;

#pragma unroll
        for (int m = 0; m < 3; ++m)
#pragma unroll
            for (int j = 0; j < 4; ++j)
                MMA_TF32(d[m][j], aa[m], bb[j]);
    }

    // ---- add bias; per-row stats (sum, sumsq, score) ----
    const int col0 = half * 32 + 2 * t;   // first col of this lane (per j add j*8)
    float2 wb2[4], aw2[4];
#pragma unroll
    for (int j = 0; j < 4; ++j) {
        wb2[j] = *(const float2*)(Wbias + col0 + j * 8);
        aw2[j] = *(const float2*)(attw + 64 + col0 + j * 8);
    }
#pragma unroll
    for (int m = 0; m < 3; ++m)
#pragma unroll
        for (int j = 0; j < 4; ++j) {
            d[m][j][0] += wb2[j].x; d[m][j][1] += wb2[j].y;
            d[m][j][2] += wb2[j].x; d[m][j][3] += wb2[j].y;
        }

    // rows held by this lane: [m][0]: m*16+g ; [m][1]: m*16+g+8
    float sm[3][2], s2[3][2], sc[3][2];
#pragma unroll
    for (int m = 0; m < 3; ++m)
#pragma unroll
        for (int rh = 0; rh < 2; ++rh) {
            float a = 0.f, q = 0.f, s = 0.f;
#pragma unroll
            for (int j = 0; j < 4; ++j) {
                float h0 = d[m][j][rh * 2], h1 = d[m][j][rh * 2 + 1];
                a += h0 + h1;
                q = fmaf(h0, h0, fmaf(h1, h1, q));
                s = fmaf(h0, aw2[j].x, fmaf(h1, aw2[j].y, s));
            }
            // quad reduce (lanes sharing g)
#pragma unroll
            for (int dl = 1; dl <= 2; dl <<= 1) {
                a += __shfl_xor_sync(0xffffffffu, a, dl);
                q += __shfl_xor_sync(0xffffffffu, q, dl);
                s += __shfl_xor_sync(0xffffffffu, s, dl);
            }
            sm[m][rh] = a; s2[m][rh] = q; sc[m][rh] = s;
        }
    if (t == 0) {
        sStats[bl][half][g]      = make_float4(sm[0][0], s2[0][0], sc[0][0], 0.f);
        sStats[bl][half][g + 8]  = make_float4(sm[0][1], s2[0][1], sc[0][1], 0.f);
        sStats[bl][half][g + 16] = make_float4(sm[1][0], s2[1][0], sc[1][0], 0.f);
        sStats[bl][half][g + 24] = make_float4(sm[1][1], s2[1][1], sc[1][1], 0.f);
        if (g == 0)
            sStats[bl][half][32] = make_float4(sm[2][0], s2[2][0], sc[2][0], 0.f);
    }
    __syncthreads();

    // ---- layernorm + store for neighbor rows (1..32) ----
    float2 g2[4], be2[4];
#pragma unroll
    for (int j = 0; j < 4; ++j) {
        g2[j]  = *(const float2*)(gamma + col0 + j * 8);
        be2[j] = *(const float2*)(beta  + col0 + j * 8);
    }
    float* gO = out + b * 2112;

#pragma unroll
    for (int m = 0; m < 3; ++m)
#pragma unroll
        for (int rh = 0; rh < 2; ++rh) {
            int row = m * 16 + g + rh * 8;
            bool valid = (row >= 1) && (row <= 32) && !(m == 2 && !(g == 0 && rh == 0));
            if (valid) {
                float4 u0 = sStats[bl][0][row];
                float4 u1 = sStats[bl][1][row];
                float mu  = (u0.x + u1.x) * (1.f / 64.f);
                float var = fmaf(u0.y + u1.y, 1.f / 64.f, -mu * mu);
                float ri  = rsqrtf(var + EPSLN);
#pragma unroll
                for (int j = 0; j < 4; ++j) {
                    float2 o;
                    o.x = fmaf((d[m][j][rh * 2]     - mu) * ri, g2[j].x, be2[j].x);
                    o.y = fmaf((d[m][j][rh * 2 + 1] - mu) * ri, g2[j].y, be2[j].y);
                    *(float2*)(gO + row * 64 + col0 + j * 8) = o;
                }
            }
        }

    // ---- softmax over 32 neighbor scores (half==0 warp of each batch) ----
    if (half == 0) {
        int row = lane + 1;
        float s = sStats[bl][0][row].z + sStats[bl][1][row].z + ek;
        float mx = s;
#pragma unroll
        for (int dl = 16; dl > 0; dl >>= 1) mx = fmaxf(mx, __shfl_xor_sync(0xffffffffu, mx, dl));
        float p = __expf(s - mx);
        float tot = p;
#pragma unroll
        for (int dl = 16; dl > 0; dl >>= 1) tot += __shfl_xor_sync(0xffffffffu, tot, dl);
        sAttn[bl][lane] = p / tot;
    }
    __syncthreads();

    // ---- messages: msg[col] = sum_k attn_k * h_k[col] ----
    float aA = (g > 0) ? sAttn[bl][g - 1] : 0.f;   // row g
    float aB = sAttn[bl][g + 7];                    // row g+8
    float aC = sAttn[bl][g + 15];                   // row 16+g
    float aD = sAttn[bl][g + 23];                   // row 24+g
    float aE = (g == 0) ? sAttn[bl][31] : 0.f;      // row 32

    float pm[4][2];
#pragma unroll
    for (int j = 0; j < 4; ++j)
#pragma unroll
        for (int c = 0; c < 2; ++c) {
            float v = aA * d[0][j][c] + aB * d[0][j][2 + c]
                    + aC * d[1][j][c] + aD * d[1][j][2 + c]
                    + aE * d[2][j][c];
#pragma unroll
            for (int dl = 4; dl <= 16; dl <<= 1)
                v += __shfl_xor_sync(0xffffffffu, v, dl);
            pm[j][c] = v;  // every lane now holds msg for its cols
        }

    // ---- target row 0 (held by g==0 lanes, regs d[0][j][0..1]) ----
    float tv[4][2];
    float tsm = 0.f, ts2 = 0.f;
#pragma unroll
    for (int j = 0; j < 4; ++j)
#pragma unroll
        for (int c = 0; c < 2; ++c) {
            float v = d[0][j][c] + pm[j][c];
            tv[j][c] = v;
            tsm += v;
            ts2 = fmaf(v, v, ts2);
        }
#pragma unroll
    for (int dl = 1; dl <= 2; dl <<= 1) {
        tsm += __shfl_xor_sync(0xffffffffu, tsm, dl);
        ts2 += __shfl_xor_sync(0xffffffffu, ts2, dl);
    }
    if (lane == 0) sT[bl][half] = make_float2(tsm, ts2);
    __syncthreads();

    if (lane < 4) {  // g==0 lanes write target row
        float2 v0 = sT[bl][0], v1 = sT[bl][1];
        float mu  = (v0.x + v1.x) * (1.f / 64.f);
        float var = fmaf(v0.y + v1.y, 1.f / 64.f, -mu * mu);
        float ri  = rsqrtf(var + EPSLN);
#pragma unroll
        for (int j = 0; j < 4; ++j) {
            float2 o;
            o.x = fmaf((tv[j][0] - mu) * ri, g2[j].x, be2[j].x);
            o.y = fmaf((tv[j][1] - mu) * ri, g2[j].y, be2[j].y);
            *(float2*)(gO + col0 + j * 8) = o;
        }
    }
}

extern "C" void kernel_launch(void* const* d_in, const int* in_sizes, int n_in,
                              void* d_out, int out_size) {
    const float* nodes = (const float*)d_in[0];
    const float* edges = (const float*)d_in[1];
    const float* Ww    = (const float*)d_in[2];
    const float* Wb    = (const float*)d_in[3];
    const float* Wew   = (const float*)d_in[4];
    // d_in[5] = We_b   (cancels under softmax shift-invariance)
    const float* attw  = (const float*)d_in[6];
    // d_in[7] = attn_b (cancels under softmax shift-invariance)
    const float* gamma = (const float*)d_in[8];
    const float* beta  = (const float*)d_in[9];

    prep_kernel<<<1, 256>>>(Ww, Wew, attw);
    gat_kernel<<<16384 / 2, 128>>>(nodes, edges, Wb, attw, gamma, beta, (float*)d_out);
}

// round 4
// speedup vs baseline: 2.4780x; 1.4854x over previous
#include <cuda_runtime.h>

#define EPSLN 1e-5f

// Precomputed per launch (deterministic, graph-capturable)
__device__ __align__(16) uint2 g_Wfrag[8 * 8 * 32];  // [ks][nt][lane] tf32 B-fragments
__device__ __align__(16) float g_ewproj[16];         // We_w @ attn_w[128:192]

__device__ __forceinline__ unsigned cvt_tf32(float x) {
    unsigned r; asm("cvt.rna.tf32.f32 %0, %1;" : "=r"(r) : "f"(x)); return r;
}

#define MMA_TF32(d, a, b)                                                          \
    asm volatile(                                                                  \
        "mma.sync.aligned.m16n8k8.row.col.f32.tf32.tf32.f32 "                      \
        "{%0,%1,%2,%3},{%4,%5,%6,%7},{%8,%9},{%0,%1,%2,%3};"                       \
        : "+f"(d[0]), "+f"(d[1]), "+f"(d[2]), "+f"(d[3])                           \
        : "r"(a[0]), "r"(a[1]), "r"(a[2]), "r"(a[3]), "r"(b[0]), "r"(b[1]))

// Named barrier over the 64 threads (2 warps) serving one batch
#define BARX(id) asm volatile("bar.sync %0, 64;" :: "r"(id) : "memory")

__global__ void prep_kernel(const float* __restrict__ Ww,
                            const float* __restrict__ Wew,
                            const float* __restrict__ attw) {
    int tid = threadIdx.x;  // 256
    if (tid < 16) {
        float se = 0.f;
#pragma unroll 8
        for (int o = 0; o < 64; ++o) se += Wew[tid * 64 + o] * attw[128 + o];
        g_ewproj[tid] = se;
    }
    // B fragment for m16n8k8.row.col: b0 = B[k=t][n=g], b1 = B[k=t+4][n=g]
    for (int idx = tid; idx < 2048; idx += 256) {
        int lane = idx & 31;
        int nt   = (idx >> 5) & 7;
        int ks   = idx >> 8;
        int t = lane & 3, g = lane >> 2;
        uint2 v;
        v.x = cvt_tf32(Ww[(ks * 8 + t) * 64 + nt * 8 + g]);
        v.y = cvt_tf32(Ww[(ks * 8 + t + 4) * 64 + nt * 8 + g]);
        g_Wfrag[idx] = v;
    }
}

__global__ __launch_bounds__(256, 3) void gat_kernel(
    const float* __restrict__ nodes,
    const float* __restrict__ edges,
    const float* __restrict__ Wbias,
    const float* __restrict__ attw,
    const float* __restrict__ gamma,
    const float* __restrict__ beta,
    float* __restrict__ out)
{
    __shared__ float  sN[4][33 * 68];        // nodes, pre-rounded to tf32
    __shared__ uint2  sB[8 * 8 * 32];        // weight fragments (16 KB)
    __shared__ float4 sStats[4][2][33];      // (sum, sumsq, score, -) per row/half
    __shared__ float  sAttn[4][32];
    __shared__ float2 sT[4][2];              // target LN partials per half

    const int tid  = threadIdx.x;
    const int lane = tid & 31;
    const int warp = tid >> 5;
    const int bl   = warp >> 1;     // batch within CTA (0..3)
    const int half = warp & 1;      // column half (32 cols)
    const int t    = lane & 3;      // threadID-in-group
    const int g    = lane >> 2;     // groupID
    const long long b = (long long)blockIdx.x * 4 + bl;
    const int barid = bl + 1;

    // ---- stage weights (all 256 threads, once per CTA / 4 batches) ----
    for (int q = tid; q < 2048; q += 256) sB[q] = g_Wfrag[q];

    // ---- stage nodes, pre-converted to tf32: 4 batches x 528 float4 ----
    const float* gNall = nodes + (long long)blockIdx.x * 4 * 2112;
#pragma unroll
    for (int bb = 0; bb < 4; ++bb) {
        const float4* src = (const float4*)(gNall + bb * 2112);
#pragma unroll
        for (int qq = 0; qq < 3; ++qq) {
            int q = tid + qq * 256;
            if (q < 528) {
                float4 v = src[q];
                float4 w;
                w.x = __uint_as_float(cvt_tf32(v.x));
                w.y = __uint_as_float(cvt_tf32(v.y));
                w.z = __uint_as_float(cvt_tf32(v.z));
                w.w = __uint_as_float(cvt_tf32(v.w));
                int r = q >> 4, i4 = q & 15;
                *(float4*)&sN[bb][r * 68 + i4 * 4] = w;
            }
        }
    }

    // ---- edge score term (half==0 warps, lane = neighbor k) ----
    float ek = 0.f;
    if (half == 0) {
        const float4* er = (const float4*)(edges + (b * 32 + lane) * 16);
#pragma unroll
        for (int e4 = 0; e4 < 4; ++e4) {
            float4 a = er[e4];
            float4 w = *(const float4*)&g_ewproj[e4 * 4];
            ek += a.x * w.x + a.y * w.y + a.z * w.z + a.w * w.w;
        }
    }

    // epilogue params (hoisted: overlap with staging latency)
    const int col0 = half * 32 + 2 * t;
    float2 wb2[4], aw2[4], g2[4], be2[4];
#pragma unroll
    for (int j = 0; j < 4; ++j) {
        wb2[j] = *(const float2*)(Wbias + col0 + j * 8);
        aw2[j] = *(const float2*)(attw + 64 + col0 + j * 8);
        g2[j]  = *(const float2*)(gamma + col0 + j * 8);
        be2[j] = *(const float2*)(beta  + col0 + j * 8);
    }

    __syncthreads();  // staging complete (CTA-wide, once)

    // ---- tensor-core GEMM: 3 m16 tiles x 4 n8 tiles (this warp's half) ----
    const unsigned* sNb = (const unsigned*)sN[bl];
    float d[3][4][4];
#pragma unroll
    for (int m = 0; m < 3; ++m)
#pragma unroll
        for (int j = 0; j < 4; ++j)
#pragma unroll
            for (int c = 0; c < 4; ++c) d[m][j][c] = 0.f;

#pragma unroll
    for (int ks = 0; ks < 8; ++ks) {
        unsigned bb[4][2];
#pragma unroll
        for (int j = 0; j < 4; ++j) {
            uint2 v = sB[(ks * 8 + half * 4 + j) * 32 + lane];
            bb[j][0] = v.x; bb[j][1] = v.y;
        }
        unsigned aa[3][4];
#pragma unroll
        for (int m = 0; m < 2; ++m) {
            int base = (m * 16 + g) * 68 + ks * 8 + t;
            aa[m][0] = sNb[base];
            aa[m][1] = sNb[base + 8 * 68];
            aa[m][2] = sNb[base + 4];
            aa[m][3] = sNb[base + 8 * 68 + 4];
        }
        if (g == 0) {   // m-tile 2: only row 32 real
            int base = 32 * 68 + ks * 8 + t;
            aa[2][0] = sNb[base];
            aa[2][2] = sNb[base + 4];
        } else { aa[2][0] = 0u; aa[2][2] = 0u; }
        aa[2][1] = 0u; aa[2][3] = 0u;

#pragma unroll
        for (int m = 0; m < 3; ++m)
#pragma unroll
            for (int j = 0; j < 4; ++j)
                MMA_TF32(d[m][j], aa[m], bb[j]);
    }

    // ---- add bias; per-row stats (sum, sumsq, score) ----
#pragma unroll
    for (int m = 0; m < 3; ++m)
#pragma unroll
        for (int j = 0; j < 4; ++j) {
            d[m][j][0] += wb2[j].x; d[m][j][1] += wb2[j].y;
            d[m][j][2] += wb2[j].x; d[m][j][3] += wb2[j].y;
        }

    float sm[3][2], s2[3][2], sc[3][2];
#pragma unroll
    for (int m = 0; m < 3; ++m)
#pragma unroll
        for (int rh = 0; rh < 2; ++rh) {
            float a = 0.f, q = 0.f, s = 0.f;
#pragma unroll
            for (int j = 0; j < 4; ++j) {
                float h0 = d[m][j][rh * 2], h1 = d[m][j][rh * 2 + 1];
                a += h0 + h1;
                q = fmaf(h0, h0, fmaf(h1, h1, q));
                s = fmaf(h0, aw2[j].x, fmaf(h1, aw2[j].y, s));
            }
#pragma unroll
            for (int dl = 1; dl <= 2; dl <<= 1) {
                a += __shfl_xor_sync(0xffffffffu, a, dl);
                q += __shfl_xor_sync(0xffffffffu, q, dl);
                s += __shfl_xor_sync(0xffffffffu, s, dl);
            }
            sm[m][rh] = a; s2[m][rh] = q; sc[m][rh] = s;
        }
    if (t == 0) {
        sStats[bl][half][g]      = make_float4(sm[0][0], s2[0][0], sc[0][0], 0.f);
        sStats[bl][half][g + 8]  = make_float4(sm[0][1], s2[0][1], sc[0][1], 0.f);
        sStats[bl][half][g + 16] = make_float4(sm[1][0], s2[1][0], sc[1][0], 0.f);
        sStats[bl][half][g + 24] = make_float4(sm[1][1], s2[1][1], sc[1][1], 0.f);
        if (g == 0)
            sStats[bl][half][32] = make_float4(sm[2][0], s2[2][0], sc[2][0], 0.f);
    }
    BARX(barid);   // only this batch's 2 warps

    // ---- layernorm + store for neighbor rows (1..32) ----
    float* gO = out + b * 2112;
#pragma unroll
    for (int m = 0; m < 3; ++m)
#pragma unroll
        for (int rh = 0; rh < 2; ++rh) {
            int row = m * 16 + g + rh * 8;
            bool valid = (row >= 1) && (row <= 32) && !(m == 2 && !(g == 0 && rh == 0));
            if (valid) {
                float4 u0 = sStats[bl][0][row];
                float4 u1 = sStats[bl][1][row];
                float mu  = (u0.x + u1.x) * (1.f / 64.f);
                float var = fmaf(u0.y + u1.y, 1.f / 64.f, -mu * mu);
                float ri  = rsqrtf(var + EPSLN);
#pragma unroll
                for (int j = 0; j < 4; ++j) {
                    float2 o;
                    o.x = fmaf((d[m][j][rh * 2]     - mu) * ri, g2[j].x, be2[j].x);
                    o.y = fmaf((d[m][j][rh * 2 + 1] - mu) * ri, g2[j].y, be2[j].y);
                    *(float2*)(gO + row * 64 + col0 + j * 8) = o;
                }
            }
        }

    // ---- softmax over 32 neighbor scores (half==0 warp of each batch) ----
    if (half == 0) {
        int row = lane + 1;
        float s = sStats[bl][0][row].z + sStats[bl][1][row].z + ek;
        float mx = s;
#pragma unroll
        for (int dl = 16; dl > 0; dl >>= 1) mx = fmaxf(mx, __shfl_xor_sync(0xffffffffu, mx, dl));
        float p = __expf(s - mx);
        float tot = p;
#pragma unroll
        for (int dl = 16; dl > 0; dl >>= 1) tot += __shfl_xor_sync(0xffffffffu, tot, dl);
        sAttn[bl][lane] = p / tot;
    }
    BARX(barid);

    // ---- messages: msg[col] = sum_k attn_k * h_k[col] ----
    float aA = (g > 0) ? sAttn[bl][g - 1] : 0.f;   // row g
    float aB = sAttn[bl][g + 7];                    // row g+8
    float aC = sAttn[bl][g + 15];                   // row 16+g
    float aD = sAttn[bl][g + 23];                   // row 24+g
    float aE = (g == 0) ? sAttn[bl][31] : 0.f;      // row 32

    float pm[4][2];
#pragma unroll
    for (int j = 0; j < 4; ++j)
#pragma unroll
        for (int c = 0; c < 2; ++c) {
            float v = aA * d[0][j][c] + aB * d[0][j][2 + c]
                    + aC * d[1][j][c] + aD * d[1][j][2 + c]
                    + aE * d[2][j][c];
#pragma unroll
            for (int dl = 4; dl <= 16; dl <<= 1)
                v += __shfl_xor_sync(0xffffffffu, v, dl);
            pm[j][c] = v;
        }

    // ---- target row 0 (held by g==0 lanes) ----
    float tv[4][2];
    float tsm = 0.f, ts2 = 0.f;
#pragma unroll
    for (int j = 0; j < 4; ++j)
#pragma unroll
        for (int c = 0; c < 2; ++c) {
            float v = d[0][j][c] + pm[j][c];
            tv[j][c] = v;
            tsm += v;
            ts2 = fmaf(v, v, ts2);
        }
#pragma unroll
    for (int dl = 1; dl <= 2; dl <<= 1) {
        tsm += __shfl_xor_sync(0xffffffffu, tsm, dl);
        ts2 += __shfl_xor_sync(0xffffffffu, ts2, dl);
    }
    if (lane == 0) sT[bl][half] = make_float2(tsm, ts2);
    BARX(barid);

    if (lane < 4) {  // g==0, t=0..3 lanes write target row
        float2 v0 = sT[bl][0], v1 = sT[bl][1];
        float mu  = (v0.x + v1.x) * (1.f / 64.f);
        float var = fmaf(v0.y + v1.y, 1.f / 64.f, -mu * mu);
        float ri  = rsqrtf(var + EPSLN);
#pragma unroll
        for (int j = 0; j < 4; ++j) {
            float2 o;
            o.x = fmaf((tv[j][0] - mu) * ri, g2[j].x, be2[j].x);
            o.y = fmaf((tv[j][1] - mu) * ri, g2[j].y, be2[j].y);
            *(float2*)(gO + col0 + j * 8) = o;
        }
    }
}

extern "C" void kernel_launch(void* const* d_in, const int* in_sizes, int n_in,
                              void* d_out, int out_size) {
    const float* nodes = (const float*)d_in[0];
    const float* edges = (const float*)d_in[1];
    const float* Ww    = (const float*)d_in[2];
    const float* Wb    = (const float*)d_in[3];
    const float* Wew   = (const float*)d_in[4];
    // d_in[5] = We_b   (cancels under softmax shift-invariance)
    const float* attw  = (const float*)d_in[6];
    // d_in[7] = attn_b (cancels under softmax shift-invariance)
    const float* gamma = (const float*)d_in[8];
    const float* beta  = (const float*)d_in[9];

    prep_kernel<<<1, 256>>>(Ww, Wew, attw);
    gat_kernel<<<16384 / 4, 256>>>(nodes, edges, Wb, attw, gamma, beta, (float*)d_out);
}